// round 14
// baseline (speedup 1.0000x reference)
#include <cuda_runtime.h>
#include <cuda_fp16.h>
#include <math.h>

// Problem constants (N,D,C,E,K = 100000,64,40,1600000,2)
#define NN 100000
#define DD 64
#define CC 40
#define EE 1600000
#define NBLK_SCAN 98             // 98*1024 >= NN, all co-resident (grid < 148)
#define R4H 8                    // uint4 (8 halves) per fp16 row

// ---- device scratch (__device__ globals; allocation APIs are banned) ----
// NOTE: g_deg relies on static zero-init for the first call; k_fill re-zeros
// it at the end of every sequence so each replay's k_count sees zeros.
__device__ int    g_deg[NN];     // edge count per row (excl self loop)
__device__ float  g_dis[NN];     // rsqrt(deg+1)
__device__ int    g_rowptr[NN + 1];
__device__ int    g_rank[EE];    // within-row rank of each edge
__device__ int    g_bsums[NBLK_SCAN];
__device__ int    g_flag[NBLK_SCAN];
__device__ int2   g_colw[EE];    // (col, half2(w,w) bits)
__device__ uint4  g_xh [(size_t)NN * R4H];   // x fp16
__device__ uint4  g_xh1[(size_t)NN * R4H];   // hop-1 output fp16

// ---------------------------------------------------------------------
// per-block dtype detect: int64 edge values must lie in [0, NN)
// ---------------------------------------------------------------------
__device__ __forceinline__ int detect_mode(const long long* ei64, int* sh_mode) {
    if (threadIdx.x < 32) {
        int bad = 0;
        #pragma unroll
        for (int k = 0; k < 2; k++) {
            long long v = ei64[threadIdx.x + k * 32];
            if (v < 0 || v >= NN) bad = 1;
        }
        unsigned ball = __ballot_sync(0xFFFFFFFFu, bad);
        if (threadIdx.x == 0) *sh_mode = ball ? 32 : 64;
    }
    __syncthreads();
    return *sh_mode;
}

// ---------------------------------------------------------------------
// 1) fused: x -> fp16 conversion, scan-flag zero, degree count + rank
// ---------------------------------------------------------------------
__global__ void __launch_bounds__(256)
k_count(const void* __restrict__ ei, const float4* __restrict__ x4, int e) {
    __shared__ int sh_mode;
    const long long* ei64 = (const long long*)ei;
    int mode = detect_mode(ei64, &sh_mode);

    int i = blockIdx.x * blockDim.x + threadIdx.x;

    if (i < NN * R4H) {
        float4 p = x4[(size_t)i * 2];
        float4 q = x4[(size_t)i * 2 + 1];
        __half2 h;
        uint4 st;
        h = __floats2half2_rn(p.x, p.y); st.x = *(unsigned*)&h;
        h = __floats2half2_rn(p.z, p.w); st.y = *(unsigned*)&h;
        h = __floats2half2_rn(q.x, q.y); st.z = *(unsigned*)&h;
        h = __floats2half2_rn(q.z, q.w); st.w = *(unsigned*)&h;
        g_xh[i] = st;
    }
    if (i < NBLK_SCAN) g_flag[i] = 0;

    int epairs = e / 2;
    if (i >= epairs) return;
    int r0, r1;
    if (mode == 64) {
        longlong2 v = ((const longlong2*)ei)[i];
        r0 = (int)v.x; r1 = (int)v.y;
    } else {
        int2 v = ((const int2*)ei)[i];
        r0 = v.x; r1 = v.y;
    }
    int k0 = atomicAdd(&g_deg[r0], 1);
    int k1 = atomicAdd(&g_deg[r1], 1);
    ((int2*)g_rank)[i] = make_int2(k0, k1);
}

// ---------------------------------------------------------------------
// 2) merged scan: block-local scan + publish-flag lookback + apply
// ---------------------------------------------------------------------
__global__ void __launch_bounds__(1024)
k_scan(int n, int e) {
    __shared__ int sh[1024];
    __shared__ int sh_off;
    int i = blockIdx.x * 1024 + threadIdx.x;
    int v = (i < n) ? g_deg[i] : 0;
    sh[threadIdx.x] = v;
    __syncthreads();
    #pragma unroll
    for (int off = 1; off < 1024; off <<= 1) {
        int t = (threadIdx.x >= off) ? sh[threadIdx.x - off] : 0;
        __syncthreads();
        sh[threadIdx.x] += t;
        __syncthreads();
    }
    int incl = sh[threadIdx.x];
    if (threadIdx.x == 1023) {
        g_bsums[blockIdx.x] = incl;
        __threadfence();
        atomicExch(&g_flag[blockIdx.x], 1);
    }
    if (threadIdx.x < 32) {
        int s = 0;
        for (int k = threadIdx.x; k < blockIdx.x; k += 32) {
            while (atomicAdd(&g_flag[k], 0) == 0) { }
            s += g_bsums[k];
        }
        #pragma unroll
        for (int o = 16; o; o >>= 1) s += __shfl_xor_sync(0xFFFFFFFFu, s, o);
        if (threadIdx.x == 0) sh_off = s;
    }
    __syncthreads();
    if (i < n) {
        g_rowptr[i] = (incl - v) + sh_off;
        g_dis[i] = rsqrtf((float)(g_deg[i] + 1));
        if (i == n - 1) g_rowptr[n] = e;
    }
}

// ---------------------------------------------------------------------
// 3) fill packed CSR + re-zero g_deg for the next replay
// ---------------------------------------------------------------------
__global__ void __launch_bounds__(256)
k_fill(const void* __restrict__ ei, int e) {
    __shared__ int sh_mode;
    const long long* ei64 = (const long long*)ei;
    int mode = detect_mode(ei64, &sh_mode);

    int i = blockIdx.x * blockDim.x + threadIdx.x;
    if (i < NN) g_deg[i] = 0;                  // reset for next replay

    int epairs = e / 2;
    if (i >= epairs) return;
    int r0, c0, r1, c1;
    if (mode == 64) {
        longlong2 rv = ((const longlong2*)ei)[i];
        longlong2 cv = ((const longlong2*)ei)[epairs + i];
        r0 = (int)rv.x; r1 = (int)rv.y;
        c0 = (int)cv.x; c1 = (int)cv.y;
    } else {
        int2 rv = ((const int2*)ei)[i];
        int2 cv = ((const int2*)ei)[epairs + i];
        r0 = rv.x; r1 = rv.y;
        c0 = cv.x; c1 = cv.y;
    }
    int2 rk = ((int2*)g_rank)[i];
    unsigned hb0 = __half_as_ushort(__float2half_rn(g_dis[c0]));
    unsigned hb1 = __half_as_ushort(__float2half_rn(g_dis[c1]));
    g_colw[g_rowptr[r0] + rk.x] = make_int2(c0, (int)(hb0 | (hb0 << 16)));
    g_colw[g_rowptr[r1] + rk.y] = make_int2(c1, (int)(hb1 | (hb1 << 16)));
}

// ---------------------------------------------------------------------
// quarter-warp fp16 gather, direct predicated edge loads, 16-edge chunks
// (EXACT R11 version — the proven-safe pattern; 32-edge chunks fault).
// 8 lanes per 128B row; lane handles edge u*4+hl. Flush every <=16 edges.
// ---------------------------------------------------------------------
__device__ __forceinline__ void
gather_row_h(const uint4* __restrict__ src, int beg, int end, int lane,
             float* a) {
    const int hl   = lane >> 3;        // edge slot within group of 4
    const int fidx = lane & 7;         // uint4 index within row
    #pragma unroll
    for (int i = 0; i < 8; i++) a[i] = 0.f;
    const __half2 z = __float2half2_rn(0.f);

    for (int base = beg; base < end; base += 16) {
        __half2 h0 = z, h1 = z, h2 = z, h3 = z;
        #pragma unroll
        for (int u = 0; u < 4; u++) {
            int s = base + u * 4 + hl;
            int c = 0; unsigned wb = 0u;       // pad: w=0 gathers row 0 harmlessly
            if (s < end) { int2 cw = g_colw[s]; c = cw.x; wb = (unsigned)cw.y; }
            __half2 w = *(__half2*)&wb;
            uint4 v = src[(size_t)c * R4H + fidx];
            h0 = __hfma2(w, *(__half2*)&v.x, h0);
            h1 = __hfma2(w, *(__half2*)&v.y, h1);
            h2 = __hfma2(w, *(__half2*)&v.z, h2);
            h3 = __hfma2(w, *(__half2*)&v.w, h3);
        }
        float2 f;
        f = __half22float2(h0); a[0] += f.x; a[1] += f.y;
        f = __half22float2(h1); a[2] += f.x; a[3] += f.y;
        f = __half22float2(h2); a[4] += f.x; a[5] += f.y;
        f = __half22float2(h3); a[6] += f.x; a[7] += f.y;
    }
    #pragma unroll
    for (int i = 0; i < 8; i++) {
        a[i] += __shfl_xor_sync(0xFFFFFFFFu, a[i], 8);
        a[i] += __shfl_xor_sync(0xFFFFFFFFu, a[i], 16);
    }
}

// ---------------------------------------------------------------------
// 4) hop 1: g_xh1[r] = fp16( dis[r]*gather(g_xh) + dis[r]^2*x[r] )
// ---------------------------------------------------------------------
__global__ void __launch_bounds__(256)
k_prop1(const float4* __restrict__ x4, int n) {
    int warp = (blockIdx.x * blockDim.x + threadIdx.x) >> 5;
    int lane = threadIdx.x & 31;
    if (warp >= n) return;

    float a[8];
    gather_row_h(g_xh, g_rowptr[warp], g_rowptr[warp + 1], lane, a);

    if (lane < 8) {
        float dr = g_dis[warp];
        float sl = dr * dr;
        float4 xa = x4[(size_t)warp * 16 + lane * 2];
        float4 xb = x4[(size_t)warp * 16 + lane * 2 + 1];
        float o0 = dr * a[0] + sl * xa.x;
        float o1 = dr * a[1] + sl * xa.y;
        float o2 = dr * a[2] + sl * xa.z;
        float o3 = dr * a[3] + sl * xa.w;
        float o4 = dr * a[4] + sl * xb.x;
        float o5 = dr * a[5] + sl * xb.y;
        float o6 = dr * a[6] + sl * xb.z;
        float o7 = dr * a[7] + sl * xb.w;
        __half2 h;
        uint4 st;
        h = __floats2half2_rn(o0, o1); st.x = *(unsigned*)&h;
        h = __floats2half2_rn(o2, o3); st.y = *(unsigned*)&h;
        h = __floats2half2_rn(o4, o5); st.z = *(unsigned*)&h;
        h = __floats2half2_rn(o6, o7); st.w = *(unsigned*)&h;
        g_xh1[(size_t)warp * R4H + lane] = st;
    }
}

// ---------------------------------------------------------------------
// 5) fused hop 2 + GEMM + log_softmax.
//    Block owns 128 rows; warp w gathers rows w*16..w*16+15 (whole warp
//    per row, uniform control flow), h written to the ldmatrix smem tile,
//    then mma.m16n8k16 epilogue.
// ---------------------------------------------------------------------
#define HS_STRIDE 9
#define WS_STRIDE 42
__global__ void __launch_bounds__(256)
k_prop2_gemm(const float* __restrict__ W, const float* __restrict__ b,
             float* __restrict__ out, int n) {
    __shared__ uint4 hs[128 * HS_STRIDE];
    __shared__ float Ws[DD * WS_STRIDE];
    __shared__ float bs[CC];

    const int tid  = threadIdx.x;
    const int warp = tid >> 5;
    const int lane = tid & 31;
    const int row0 = blockIdx.x * 128;

    for (int i = tid; i < DD * CC; i += 256) {
        int k = i / CC, c = i % CC;
        Ws[k * WS_STRIDE + c] = W[i];
    }
    if (tid < CC) bs[tid] = b[tid];

    // ---- hop 2 for this block's 128 rows ----
    for (int rr = 0; rr < 16; rr++) {
        int r = warp * 16 + rr;
        int row = row0 + r;
        if (row < n) {
            float a[8];
            gather_row_h(g_xh1, g_rowptr[row], g_rowptr[row + 1], lane, a);
            if (lane < 8) {
                float dr = g_dis[row];
                float sl = dr * dr;
                uint4 xs = g_xh1[(size_t)row * R4H + lane];
                float2 f0 = __half22float2(*(__half2*)&xs.x);
                float2 f1 = __half22float2(*(__half2*)&xs.y);
                float2 f2 = __half22float2(*(__half2*)&xs.z);
                float2 f3 = __half22float2(*(__half2*)&xs.w);
                float o0 = dr * a[0] + sl * f0.x;
                float o1 = dr * a[1] + sl * f0.y;
                float o2 = dr * a[2] + sl * f1.x;
                float o3 = dr * a[3] + sl * f1.y;
                float o4 = dr * a[4] + sl * f2.x;
                float o5 = dr * a[5] + sl * f2.y;
                float o6 = dr * a[6] + sl * f3.x;
                float o7 = dr * a[7] + sl * f3.y;
                __half2 h;
                uint4 st;
                h = __floats2half2_rn(o0, o1); st.x = *(unsigned*)&h;
                h = __floats2half2_rn(o2, o3); st.y = *(unsigned*)&h;
                h = __floats2half2_rn(o4, o5); st.z = *(unsigned*)&h;
                h = __floats2half2_rn(o6, o7); st.w = *(unsigned*)&h;
                hs[r * HS_STRIDE + lane] = st;
            }
        } else if (lane < 8) {
            hs[r * HS_STRIDE + lane] = make_uint4(0u, 0u, 0u, 0u);
        }
    }
    __syncthreads();

    // ---- A fragments via ldmatrix ----
    unsigned hs_base = (unsigned)__cvta_generic_to_shared(hs);
    unsigned A[4][4];
    {
        int r_in = lane & 15;
        int half16 = (lane >> 4) * 16;
        unsigned rowaddr = hs_base + (unsigned)((warp * 16 + r_in) * (HS_STRIDE * 16)) + half16;
        #pragma unroll
        for (int kt = 0; kt < 4; kt++) {
            unsigned addr = rowaddr + kt * 32;
            asm volatile("ldmatrix.sync.aligned.m8n8.x4.shared.b16 {%0,%1,%2,%3}, [%4];"
                         : "=r"(A[kt][0]), "=r"(A[kt][1]), "=r"(A[kt][2]), "=r"(A[kt][3])
                         : "r"(addr));
        }
    }

    const int t = lane & 3, g = lane >> 2;
    float C[5][4];
    #pragma unroll
    for (int nt = 0; nt < 5; nt++) {
        int col0 = nt * 8 + 2 * t;
        float bi0 = bs[col0], bi1 = bs[col0 + 1];
        C[nt][0] = bi0; C[nt][1] = bi1; C[nt][2] = bi0; C[nt][3] = bi1;
        int nn = nt * 8 + g;
        #pragma unroll
        for (int kt = 0; kt < 4; kt++) {
            int k0 = kt * 16 + 2 * t;
            __half2 hb0 = __floats2half2_rn(Ws[k0 * WS_STRIDE + nn],
                                            Ws[(k0 + 1) * WS_STRIDE + nn]);
            __half2 hb1 = __floats2half2_rn(Ws[(k0 + 8) * WS_STRIDE + nn],
                                            Ws[(k0 + 9) * WS_STRIDE + nn]);
            unsigned B0 = *(unsigned*)&hb0;
            unsigned B1 = *(unsigned*)&hb1;
            asm volatile(
                "mma.sync.aligned.m16n8k16.row.col.f32.f16.f16.f32 "
                "{%0,%1,%2,%3}, {%4,%5,%6,%7}, {%8,%9}, {%0,%1,%2,%3};"
                : "+f"(C[nt][0]), "+f"(C[nt][1]), "+f"(C[nt][2]), "+f"(C[nt][3])
                : "r"(A[kt][0]), "r"(A[kt][1]), "r"(A[kt][2]), "r"(A[kt][3]),
                  "r"(B0), "r"(B1));
        }
    }

    float m0 = -1e30f, m1 = -1e30f;
    #pragma unroll
    for (int nt = 0; nt < 5; nt++) {
        m0 = fmaxf(m0, fmaxf(C[nt][0], C[nt][1]));
        m1 = fmaxf(m1, fmaxf(C[nt][2], C[nt][3]));
    }
    m0 = fmaxf(m0, __shfl_xor_sync(0xFFFFFFFFu, m0, 1));
    m0 = fmaxf(m0, __shfl_xor_sync(0xFFFFFFFFu, m0, 2));
    m1 = fmaxf(m1, __shfl_xor_sync(0xFFFFFFFFu, m1, 1));
    m1 = fmaxf(m1, __shfl_xor_sync(0xFFFFFFFFu, m1, 2));

    float s0 = 0.f, s1 = 0.f;
    #pragma unroll
    for (int nt = 0; nt < 5; nt++) {
        s0 += __expf(C[nt][0] - m0) + __expf(C[nt][1] - m0);
        s1 += __expf(C[nt][2] - m1) + __expf(C[nt][3] - m1);
    }
    s0 += __shfl_xor_sync(0xFFFFFFFFu, s0, 1);
    s0 += __shfl_xor_sync(0xFFFFFFFFu, s0, 2);
    s1 += __shfl_xor_sync(0xFFFFFFFFu, s1, 1);
    s1 += __shfl_xor_sync(0xFFFFFFFFu, s1, 2);

    float lse0 = m0 + __logf(s0);
    float lse1 = m1 + __logf(s1);

    int grow0 = row0 + warp * 16 + g;
    int grow1 = grow0 + 8;
    #pragma unroll
    for (int nt = 0; nt < 5; nt++) {
        int col0 = nt * 8 + 2 * t;
        if (grow0 < n)
            *(float2*)(out + (size_t)grow0 * CC + col0) =
                make_float2(C[nt][0] - lse0, C[nt][1] - lse0);
        if (grow1 < n)
            *(float2*)(out + (size_t)grow1 * CC + col0) =
                make_float2(C[nt][2] - lse1, C[nt][3] - lse1);
    }
}

// ---------------------------------------------------------------------
extern "C" void kernel_launch(void* const* d_in, const int* in_sizes, int n_in,
                              void* d_out, int out_size) {
    const float* x  = (const float*)d_in[0];
    const void*  ei = (const void*)d_in[1];
    const float* W  = (const float*)d_in[2];
    const float* b  = (const float*)d_in[3];
    float* out = (float*)d_out;

    const int n = NN, e = EE;
    const int T = 256;
    const int epairs = e / 2;               // 800000 == NN*R4H

    k_count     <<<(epairs + T - 1) / T, T>>>(ei, (const float4*)x, e);
    k_scan      <<<NBLK_SCAN, 1024>>>(n, e);
    k_fill      <<<(epairs + T - 1) / T, T>>>(ei, e);

    int prop_blocks = (n * 32 + T - 1) / T;   // warp per row
    k_prop1     <<<prop_blocks, T>>>((const float4*)x, n);
    k_prop2_gemm<<<(n + 127) / 128, T>>>(W, b, out, n);
}

// round 15
// speedup vs baseline: 1.0197x; 1.0197x over previous
#include <cuda_runtime.h>
#include <cuda_fp16.h>
#include <math.h>

// Problem constants (N,D,C,E,K = 100000,64,40,1600000,2)
#define NN 100000
#define DD 64
#define CC 40
#define EE 1600000
#define NBLK_SCAN 98             // 98*1024 >= NN, all co-resident (grid < 148)
#define R4H 8                    // uint4 (8 halves) per fp16 row

// ---- device scratch (__device__ globals; allocation APIs are banned) ----
// NOTE: g_deg relies on static zero-init for the first call; k_fill re-zeros
// it at the end of every sequence so each replay's k_count sees zeros.
__device__ int    g_deg[NN];     // edge count per row (excl self loop)
__device__ float  g_dis[NN];     // rsqrt(deg+1)
__device__ int    g_rowptr[NN + 1];
__device__ int    g_rank[EE];    // within-row rank of each edge
__device__ int    g_bsums[NBLK_SCAN];
__device__ int    g_flag[NBLK_SCAN];
__device__ int2   g_colw[EE];    // (col, half2(w,w) bits)
__device__ uint4  g_xh [(size_t)NN * R4H];   // x fp16
__device__ uint4  g_xh1[(size_t)NN * R4H];   // hop-1 output fp16

// ---------------------------------------------------------------------
// per-block dtype detect: int64 edge values must lie in [0, NN)
// ---------------------------------------------------------------------
__device__ __forceinline__ int detect_mode(const long long* ei64, int* sh_mode) {
    if (threadIdx.x < 32) {
        int bad = 0;
        #pragma unroll
        for (int k = 0; k < 2; k++) {
            long long v = ei64[threadIdx.x + k * 32];
            if (v < 0 || v >= NN) bad = 1;
        }
        unsigned ball = __ballot_sync(0xFFFFFFFFu, bad);
        if (threadIdx.x == 0) *sh_mode = ball ? 32 : 64;
    }
    __syncthreads();
    return *sh_mode;
}

// ---------------------------------------------------------------------
// 1) fused: x -> fp16 conversion, scan-flag zero, degree count + rank
// ---------------------------------------------------------------------
__global__ void __launch_bounds__(256)
k_count(const void* __restrict__ ei, const float4* __restrict__ x4, int e) {
    __shared__ int sh_mode;
    const long long* ei64 = (const long long*)ei;
    int mode = detect_mode(ei64, &sh_mode);

    int i = blockIdx.x * blockDim.x + threadIdx.x;

    if (i < NN * R4H) {
        float4 p = x4[(size_t)i * 2];
        float4 q = x4[(size_t)i * 2 + 1];
        __half2 h;
        uint4 st;
        h = __floats2half2_rn(p.x, p.y); st.x = *(unsigned*)&h;
        h = __floats2half2_rn(p.z, p.w); st.y = *(unsigned*)&h;
        h = __floats2half2_rn(q.x, q.y); st.z = *(unsigned*)&h;
        h = __floats2half2_rn(q.z, q.w); st.w = *(unsigned*)&h;
        g_xh[i] = st;
    }
    if (i < NBLK_SCAN) g_flag[i] = 0;

    int epairs = e / 2;
    if (i >= epairs) return;
    int r0, r1;
    if (mode == 64) {
        longlong2 v = ((const longlong2*)ei)[i];
        r0 = (int)v.x; r1 = (int)v.y;
    } else {
        int2 v = ((const int2*)ei)[i];
        r0 = v.x; r1 = v.y;
    }
    int k0 = atomicAdd(&g_deg[r0], 1);
    int k1 = atomicAdd(&g_deg[r1], 1);
    ((int2*)g_rank)[i] = make_int2(k0, k1);
}

// ---------------------------------------------------------------------
// 2) merged scan: block-local scan + publish-flag lookback + apply
// ---------------------------------------------------------------------
__global__ void __launch_bounds__(1024)
k_scan(int n, int e) {
    __shared__ int sh[1024];
    __shared__ int sh_off;
    int i = blockIdx.x * 1024 + threadIdx.x;
    int v = (i < n) ? g_deg[i] : 0;
    sh[threadIdx.x] = v;
    __syncthreads();
    #pragma unroll
    for (int off = 1; off < 1024; off <<= 1) {
        int t = (threadIdx.x >= off) ? sh[threadIdx.x - off] : 0;
        __syncthreads();
        sh[threadIdx.x] += t;
        __syncthreads();
    }
    int incl = sh[threadIdx.x];
    if (threadIdx.x == 1023) {
        g_bsums[blockIdx.x] = incl;
        __threadfence();
        atomicExch(&g_flag[blockIdx.x], 1);
    }
    if (threadIdx.x < 32) {
        int s = 0;
        for (int k = threadIdx.x; k < blockIdx.x; k += 32) {
            while (atomicAdd(&g_flag[k], 0) == 0) { }
            s += g_bsums[k];
        }
        #pragma unroll
        for (int o = 16; o; o >>= 1) s += __shfl_xor_sync(0xFFFFFFFFu, s, o);
        if (threadIdx.x == 0) sh_off = s;
    }
    __syncthreads();
    if (i < n) {
        g_rowptr[i] = (incl - v) + sh_off;
        g_dis[i] = rsqrtf((float)(g_deg[i] + 1));
        if (i == n - 1) g_rowptr[n] = e;
    }
}

// ---------------------------------------------------------------------
// 3) fill packed CSR + re-zero g_deg for the next replay
// ---------------------------------------------------------------------
__global__ void __launch_bounds__(256)
k_fill(const void* __restrict__ ei, int e) {
    __shared__ int sh_mode;
    const long long* ei64 = (const long long*)ei;
    int mode = detect_mode(ei64, &sh_mode);

    int i = blockIdx.x * blockDim.x + threadIdx.x;
    if (i < NN) g_deg[i] = 0;                  // reset for next replay

    int epairs = e / 2;
    if (i >= epairs) return;
    int r0, c0, r1, c1;
    if (mode == 64) {
        longlong2 rv = ((const longlong2*)ei)[i];
        longlong2 cv = ((const longlong2*)ei)[epairs + i];
        r0 = (int)rv.x; r1 = (int)rv.y;
        c0 = (int)cv.x; c1 = (int)cv.y;
    } else {
        int2 rv = ((const int2*)ei)[i];
        int2 cv = ((const int2*)ei)[epairs + i];
        r0 = rv.x; r1 = rv.y;
        c0 = cv.x; c1 = cv.y;
    }
    int2 rk = ((int2*)g_rank)[i];
    unsigned hb0 = __half_as_ushort(__float2half_rn(g_dis[c0]));
    unsigned hb1 = __half_as_ushort(__float2half_rn(g_dis[c1]));
    g_colw[g_rowptr[r0] + rk.x] = make_int2(c0, (int)(hb0 | (hb0 << 16)));
    g_colw[g_rowptr[r1] + rk.y] = make_int2(c1, (int)(hb1 | (hb1 << 16)));
}

// ---------------------------------------------------------------------
// quarter-warp fp16 gather, direct predicated edge loads, 16-edge chunks
// (proven-safe; 32-edge chunks fault — recorded no-go).
// 8 lanes per 128B row; lane handles edge u*4+hl. Flush every <=16 edges.
// ---------------------------------------------------------------------
__device__ __forceinline__ void
gather_row_h(const uint4* __restrict__ src, int beg, int end, int lane,
             float* a) {
    const int hl   = lane >> 3;        // edge slot within group of 4
    const int fidx = lane & 7;         // uint4 index within row
    #pragma unroll
    for (int i = 0; i < 8; i++) a[i] = 0.f;
    const __half2 z = __float2half2_rn(0.f);

    for (int base = beg; base < end; base += 16) {
        __half2 h0 = z, h1 = z, h2 = z, h3 = z;
        #pragma unroll
        for (int u = 0; u < 4; u++) {
            int s = base + u * 4 + hl;
            int c = 0; unsigned wb = 0u;       // pad: w=0 gathers row 0 harmlessly
            if (s < end) { int2 cw = g_colw[s]; c = cw.x; wb = (unsigned)cw.y; }
            __half2 w = *(__half2*)&wb;
            uint4 v = src[(size_t)c * R4H + fidx];
            h0 = __hfma2(w, *(__half2*)&v.x, h0);
            h1 = __hfma2(w, *(__half2*)&v.y, h1);
            h2 = __hfma2(w, *(__half2*)&v.z, h2);
            h3 = __hfma2(w, *(__half2*)&v.w, h3);
        }
        float2 f;
        f = __half22float2(h0); a[0] += f.x; a[1] += f.y;
        f = __half22float2(h1); a[2] += f.x; a[3] += f.y;
        f = __half22float2(h2); a[4] += f.x; a[5] += f.y;
        f = __half22float2(h3); a[6] += f.x; a[7] += f.y;
    }
    #pragma unroll
    for (int i = 0; i < 8; i++) {
        a[i] += __shfl_xor_sync(0xFFFFFFFFu, a[i], 8);
        a[i] += __shfl_xor_sync(0xFFFFFFFFu, a[i], 16);
    }
}

// ---------------------------------------------------------------------
// 4) hop 1: g_xh1[r] = fp16( dis[r]*gather(g_xh) + dis[r]^2*x[r] )
//    128-thread blocks: 13 blocks/SM at 38 regs (81% theoretical occ)
//    and finer-grained completion (4 rows/block vs 8).
// ---------------------------------------------------------------------
__global__ void __launch_bounds__(128)
k_prop1(const float4* __restrict__ x4, int n) {
    int warp = (blockIdx.x * blockDim.x + threadIdx.x) >> 5;
    int lane = threadIdx.x & 31;
    if (warp >= n) return;

    float a[8];
    gather_row_h(g_xh, g_rowptr[warp], g_rowptr[warp + 1], lane, a);

    if (lane < 8) {
        float dr = g_dis[warp];
        float sl = dr * dr;
        float4 xa = x4[(size_t)warp * 16 + lane * 2];
        float4 xb = x4[(size_t)warp * 16 + lane * 2 + 1];
        float o0 = dr * a[0] + sl * xa.x;
        float o1 = dr * a[1] + sl * xa.y;
        float o2 = dr * a[2] + sl * xa.z;
        float o3 = dr * a[3] + sl * xa.w;
        float o4 = dr * a[4] + sl * xb.x;
        float o5 = dr * a[5] + sl * xb.y;
        float o6 = dr * a[6] + sl * xb.z;
        float o7 = dr * a[7] + sl * xb.w;
        __half2 h;
        uint4 st;
        h = __floats2half2_rn(o0, o1); st.x = *(unsigned*)&h;
        h = __floats2half2_rn(o2, o3); st.y = *(unsigned*)&h;
        h = __floats2half2_rn(o4, o5); st.z = *(unsigned*)&h;
        h = __floats2half2_rn(o6, o7); st.w = *(unsigned*)&h;
        g_xh1[(size_t)warp * R4H + lane] = st;
    }
}

// ---------------------------------------------------------------------
// 5) fused hop 2 + GEMM + log_softmax.
//    Block owns 128 rows; warp w gathers rows w*16..w*16+15 (whole warp
//    per row, uniform control flow), h written to the ldmatrix smem tile,
//    then mma.m16n8k16 epilogue.
// ---------------------------------------------------------------------
#define HS_STRIDE 9
#define WS_STRIDE 42
__global__ void __launch_bounds__(256)
k_prop2_gemm(const float* __restrict__ W, const float* __restrict__ b,
             float* __restrict__ out, int n) {
    __shared__ uint4 hs[128 * HS_STRIDE];
    __shared__ float Ws[DD * WS_STRIDE];
    __shared__ float bs[CC];

    const int tid  = threadIdx.x;
    const int warp = tid >> 5;
    const int lane = tid & 31;
    const int row0 = blockIdx.x * 128;

    for (int i = tid; i < DD * CC; i += 256) {
        int k = i / CC, c = i % CC;
        Ws[k * WS_STRIDE + c] = W[i];
    }
    if (tid < CC) bs[tid] = b[tid];

    // ---- hop 2 for this block's 128 rows ----
    for (int rr = 0; rr < 16; rr++) {
        int r = warp * 16 + rr;
        int row = row0 + r;
        if (row < n) {
            float a[8];
            gather_row_h(g_xh1, g_rowptr[row], g_rowptr[row + 1], lane, a);
            if (lane < 8) {
                float dr = g_dis[row];
                float sl = dr * dr;
                uint4 xs = g_xh1[(size_t)row * R4H + lane];
                float2 f0 = __half22float2(*(__half2*)&xs.x);
                float2 f1 = __half22float2(*(__half2*)&xs.y);
                float2 f2 = __half22float2(*(__half2*)&xs.z);
                float2 f3 = __half22float2(*(__half2*)&xs.w);
                float o0 = dr * a[0] + sl * f0.x;
                float o1 = dr * a[1] + sl * f0.y;
                float o2 = dr * a[2] + sl * f1.x;
                float o3 = dr * a[3] + sl * f1.y;
                float o4 = dr * a[4] + sl * f2.x;
                float o5 = dr * a[5] + sl * f2.y;
                float o6 = dr * a[6] + sl * f3.x;
                float o7 = dr * a[7] + sl * f3.y;
                __half2 h;
                uint4 st;
                h = __floats2half2_rn(o0, o1); st.x = *(unsigned*)&h;
                h = __floats2half2_rn(o2, o3); st.y = *(unsigned*)&h;
                h = __floats2half2_rn(o4, o5); st.z = *(unsigned*)&h;
                h = __floats2half2_rn(o6, o7); st.w = *(unsigned*)&h;
                hs[r * HS_STRIDE + lane] = st;
            }
        } else if (lane < 8) {
            hs[r * HS_STRIDE + lane] = make_uint4(0u, 0u, 0u, 0u);
        }
    }
    __syncthreads();

    // ---- A fragments via ldmatrix ----
    unsigned hs_base = (unsigned)__cvta_generic_to_shared(hs);
    unsigned A[4][4];
    {
        int r_in = lane & 15;
        int half16 = (lane >> 4) * 16;
        unsigned rowaddr = hs_base + (unsigned)((warp * 16 + r_in) * (HS_STRIDE * 16)) + half16;
        #pragma unroll
        for (int kt = 0; kt < 4; kt++) {
            unsigned addr = rowaddr + kt * 32;
            asm volatile("ldmatrix.sync.aligned.m8n8.x4.shared.b16 {%0,%1,%2,%3}, [%4];"
                         : "=r"(A[kt][0]), "=r"(A[kt][1]), "=r"(A[kt][2]), "=r"(A[kt][3])
                         : "r"(addr));
        }
    }

    const int t = lane & 3, g = lane >> 2;
    float C[5][4];
    #pragma unroll
    for (int nt = 0; nt < 5; nt++) {
        int col0 = nt * 8 + 2 * t;
        float bi0 = bs[col0], bi1 = bs[col0 + 1];
        C[nt][0] = bi0; C[nt][1] = bi1; C[nt][2] = bi0; C[nt][3] = bi1;
        int nn = nt * 8 + g;
        #pragma unroll
        for (int kt = 0; kt < 4; kt++) {
            int k0 = kt * 16 + 2 * t;
            __half2 hb0 = __floats2half2_rn(Ws[k0 * WS_STRIDE + nn],
                                            Ws[(k0 + 1) * WS_STRIDE + nn]);
            __half2 hb1 = __floats2half2_rn(Ws[(k0 + 8) * WS_STRIDE + nn],
                                            Ws[(k0 + 9) * WS_STRIDE + nn]);
            unsigned B0 = *(unsigned*)&hb0;
            unsigned B1 = *(unsigned*)&hb1;
            asm volatile(
                "mma.sync.aligned.m16n8k16.row.col.f32.f16.f16.f32 "
                "{%0,%1,%2,%3}, {%4,%5,%6,%7}, {%8,%9}, {%0,%1,%2,%3};"
                : "+f"(C[nt][0]), "+f"(C[nt][1]), "+f"(C[nt][2]), "+f"(C[nt][3])
                : "r"(A[kt][0]), "r"(A[kt][1]), "r"(A[kt][2]), "r"(A[kt][3]),
                  "r"(B0), "r"(B1));
        }
    }

    float m0 = -1e30f, m1 = -1e30f;
    #pragma unroll
    for (int nt = 0; nt < 5; nt++) {
        m0 = fmaxf(m0, fmaxf(C[nt][0], C[nt][1]));
        m1 = fmaxf(m1, fmaxf(C[nt][2], C[nt][3]));
    }
    m0 = fmaxf(m0, __shfl_xor_sync(0xFFFFFFFFu, m0, 1));
    m0 = fmaxf(m0, __shfl_xor_sync(0xFFFFFFFFu, m0, 2));
    m1 = fmaxf(m1, __shfl_xor_sync(0xFFFFFFFFu, m1, 1));
    m1 = fmaxf(m1, __shfl_xor_sync(0xFFFFFFFFu, m1, 2));

    float s0 = 0.f, s1 = 0.f;
    #pragma unroll
    for (int nt = 0; nt < 5; nt++) {
        s0 += __expf(C[nt][0] - m0) + __expf(C[nt][1] - m0);
        s1 += __expf(C[nt][2] - m1) + __expf(C[nt][3] - m1);
    }
    s0 += __shfl_xor_sync(0xFFFFFFFFu, s0, 1);
    s0 += __shfl_xor_sync(0xFFFFFFFFu, s0, 2);
    s1 += __shfl_xor_sync(0xFFFFFFFFu, s1, 1);
    s1 += __shfl_xor_sync(0xFFFFFFFFu, s1, 2);

    float lse0 = m0 + __logf(s0);
    float lse1 = m1 + __logf(s1);

    int grow0 = row0 + warp * 16 + g;
    int grow1 = grow0 + 8;
    #pragma unroll
    for (int nt = 0; nt < 5; nt++) {
        int col0 = nt * 8 + 2 * t;
        if (grow0 < n)
            *(float2*)(out + (size_t)grow0 * CC + col0) =
                make_float2(C[nt][0] - lse0, C[nt][1] - lse0);
        if (grow1 < n)
            *(float2*)(out + (size_t)grow1 * CC + col0) =
                make_float2(C[nt][2] - lse1, C[nt][3] - lse1);
    }
}

// ---------------------------------------------------------------------
extern "C" void kernel_launch(void* const* d_in, const int* in_sizes, int n_in,
                              void* d_out, int out_size) {
    const float* x  = (const float*)d_in[0];
    const void*  ei = (const void*)d_in[1];
    const float* W  = (const float*)d_in[2];
    const float* b  = (const float*)d_in[3];
    float* out = (float*)d_out;

    const int n = NN, e = EE;
    const int T = 256;
    const int epairs = e / 2;               // 800000 == NN*R4H

    k_count     <<<(epairs + T - 1) / T, T>>>(ei, (const float4*)x, e);
    k_scan      <<<NBLK_SCAN, 1024>>>(n, e);
    k_fill      <<<(epairs + T - 1) / T, T>>>(ei, e);

    int prop_blocks = (n * 32 + 127) / 128;   // warp per row, 128-thread blocks
    k_prop1     <<<prop_blocks, 128>>>((const float4*)x, n);
    k_prop2_gemm<<<(n + 127) / 128, T>>>(W, b, out, n);
}

// round 16
// speedup vs baseline: 1.0891x; 1.0681x over previous
#include <cuda_runtime.h>
#include <cuda_fp16.h>
#include <math.h>

// Problem constants (N,D,C,E,K = 100000,64,40,1600000,2)
#define NN 100000
#define DD 64
#define CC 40
#define EE 1600000
#define NBLK_SCAN 98             // 98*1024 >= NN, all co-resident (grid < 148)
#define R4H 8                    // uint4 (8 halves) per fp16 row

// ---- device scratch (__device__ globals; allocation APIs are banned) ----
// NOTE: g_deg relies on static zero-init for the first call; k_fill re-zeros
// it at the end of every sequence so each replay's k_count sees zeros.
__device__ int    g_deg[NN];     // edge count per row (excl self loop)
__device__ float  g_dis[NN];     // rsqrt(deg+1)
__device__ int    g_rowptr[NN + 1];
__device__ int    g_rank[EE];    // within-row rank of each edge
__device__ int    g_bsums[NBLK_SCAN];
__device__ int    g_flag[NBLK_SCAN];
__device__ int    g_col[EE];     // CSR cols only (4B/edge)
// feature buffers have one extra all-zero row (index NN) for gather padding
__device__ uint4  g_xh [(size_t)(NN + 1) * R4H];   // y  = dis*x   (fp16)
__device__ uint4  g_xh1[(size_t)(NN + 1) * R4H];   // y1 = dis*h1  (fp16)

// ---------------------------------------------------------------------
// per-block dtype detect: int64 edge values must lie in [0, NN)
// ---------------------------------------------------------------------
__device__ __forceinline__ int detect_mode(const long long* ei64, int* sh_mode) {
    if (threadIdx.x < 32) {
        int bad = 0;
        #pragma unroll
        for (int k = 0; k < 2; k++) {
            long long v = ei64[threadIdx.x + k * 32];
            if (v < 0 || v >= NN) bad = 1;
        }
        unsigned ball = __ballot_sync(0xFFFFFFFFu, bad);
        if (threadIdx.x == 0) *sh_mode = ball ? 32 : 64;
    }
    __syncthreads();
    return *sh_mode;
}

// ---------------------------------------------------------------------
// 1) degree count + rank + scan-flag zero
// ---------------------------------------------------------------------
__global__ void __launch_bounds__(256)
k_count(const void* __restrict__ ei, int e) {
    __shared__ int sh_mode;
    const long long* ei64 = (const long long*)ei;
    int mode = detect_mode(ei64, &sh_mode);

    int i = blockIdx.x * blockDim.x + threadIdx.x;
    if (i < NBLK_SCAN) g_flag[i] = 0;

    int epairs = e / 2;
    if (i >= epairs) return;
    int r0, r1;
    if (mode == 64) {
        longlong2 v = ((const longlong2*)ei)[i];
        r0 = (int)v.x; r1 = (int)v.y;
    } else {
        int2 v = ((const int2*)ei)[i];
        r0 = v.x; r1 = v.y;
    }
    int k0 = atomicAdd(&g_deg[r0], 1);
    int k1 = atomicAdd(&g_deg[r1], 1);
    ((int2*)g_rank)[i] = make_int2(k0, k1);
}

// ---------------------------------------------------------------------
// 2) merged scan: block-local scan + publish-flag lookback + apply
// ---------------------------------------------------------------------
__global__ void __launch_bounds__(1024)
k_scan(int n, int e) {
    __shared__ int sh[1024];
    __shared__ int sh_off;
    int i = blockIdx.x * 1024 + threadIdx.x;
    int v = (i < n) ? g_deg[i] : 0;
    sh[threadIdx.x] = v;
    __syncthreads();
    #pragma unroll
    for (int off = 1; off < 1024; off <<= 1) {
        int t = (threadIdx.x >= off) ? sh[threadIdx.x - off] : 0;
        __syncthreads();
        sh[threadIdx.x] += t;
        __syncthreads();
    }
    int incl = sh[threadIdx.x];
    if (threadIdx.x == 1023) {
        g_bsums[blockIdx.x] = incl;
        __threadfence();
        atomicExch(&g_flag[blockIdx.x], 1);
    }
    if (threadIdx.x < 32) {
        int s = 0;
        for (int k = threadIdx.x; k < blockIdx.x; k += 32) {
            while (atomicAdd(&g_flag[k], 0) == 0) { }
            s += g_bsums[k];
        }
        #pragma unroll
        for (int o = 16; o; o >>= 1) s += __shfl_xor_sync(0xFFFFFFFFu, s, o);
        if (threadIdx.x == 0) sh_off = s;
    }
    __syncthreads();
    if (i < n) {
        g_rowptr[i] = (incl - v) + sh_off;
        g_dis[i] = rsqrtf((float)(g_deg[i] + 1));
        if (i == n - 1) g_rowptr[n] = e;
    }
}

// ---------------------------------------------------------------------
// 3) fill: y = fp16(dis*x) conversion, zero pad rows, col-only CSR fill,
//    re-zero g_deg for the next replay. No random dis gathers.
// ---------------------------------------------------------------------
__global__ void __launch_bounds__(256)
k_fill(const void* __restrict__ ei, const float4* __restrict__ x4, int e) {
    __shared__ int sh_mode;
    const long long* ei64 = (const long long*)ei;
    int mode = detect_mode(ei64, &sh_mode);

    int i = blockIdx.x * blockDim.x + threadIdx.x;

    // y conversion: i indexes uint4 rows (NN*R4H = 800000)
    if (i < NN * R4H) {
        int row = i >> 3;                       // R4H = 8
        float ds = g_dis[row];
        float4 p = x4[(size_t)i * 2];
        float4 q = x4[(size_t)i * 2 + 1];
        __half2 h;
        uint4 st;
        h = __floats2half2_rn(ds * p.x, ds * p.y); st.x = *(unsigned*)&h;
        h = __floats2half2_rn(ds * p.z, ds * p.w); st.y = *(unsigned*)&h;
        h = __floats2half2_rn(ds * q.x, ds * q.y); st.z = *(unsigned*)&h;
        h = __floats2half2_rn(ds * q.z, ds * q.w); st.w = *(unsigned*)&h;
        g_xh[i] = st;
    }
    if (i < R4H) {                              // zero pad rows (index NN)
        g_xh [(size_t)NN * R4H + i] = make_uint4(0u, 0u, 0u, 0u);
        g_xh1[(size_t)NN * R4H + i] = make_uint4(0u, 0u, 0u, 0u);
    }
    if (i < NN) g_deg[i] = 0;                   // reset for next replay

    int epairs = e / 2;
    if (i >= epairs) return;
    int r0, c0, r1, c1;
    if (mode == 64) {
        longlong2 rv = ((const longlong2*)ei)[i];
        longlong2 cv = ((const longlong2*)ei)[epairs + i];
        r0 = (int)rv.x; r1 = (int)rv.y;
        c0 = (int)cv.x; c1 = (int)cv.y;
    } else {
        int2 rv = ((const int2*)ei)[i];
        int2 cv = ((const int2*)ei)[epairs + i];
        r0 = rv.x; r1 = rv.y;
        c0 = cv.x; c1 = cv.y;
    }
    int2 rk = ((int2*)g_rank)[i];
    g_col[g_rowptr[r0] + rk.x] = c0;
    g_col[g_rowptr[r1] + rk.y] = c1;
}

// ---------------------------------------------------------------------
// quarter-warp fp16 gather of pre-scaled features: a = sum_c y[c].
// 8 lanes per 128B row; lane handles edge u*4+hl; out-of-range edges
// map to the zero pad row (c = NN) so the feature load is unconditional.
// Proven 16-edge/4-unroll structure. Flush to fp32 every <=16 edges.
// ---------------------------------------------------------------------
__device__ __forceinline__ void
gather_row_h(const uint4* __restrict__ src, int beg, int end, int lane,
             float* a) {
    const int hl   = lane >> 3;        // edge slot within group of 4
    const int fidx = lane & 7;         // uint4 index within row
    #pragma unroll
    for (int i = 0; i < 8; i++) a[i] = 0.f;
    const __half2 z = __float2half2_rn(0.f);

    for (int base = beg; base < end; base += 16) {
        __half2 h0 = z, h1 = z, h2 = z, h3 = z;
        #pragma unroll
        for (int u = 0; u < 4; u++) {
            int s = base + u * 4 + hl;
            int c = NN;                         // pad row: all zeros
            if (s < end) c = g_col[s];
            uint4 v = src[(size_t)c * R4H + fidx];
            h0 = __hadd2(h0, *(__half2*)&v.x);
            h1 = __hadd2(h1, *(__half2*)&v.y);
            h2 = __hadd2(h2, *(__half2*)&v.z);
            h3 = __hadd2(h3, *(__half2*)&v.w);
        }
        float2 f;
        f = __half22float2(h0); a[0] += f.x; a[1] += f.y;
        f = __half22float2(h1); a[2] += f.x; a[3] += f.y;
        f = __half22float2(h2); a[4] += f.x; a[5] += f.y;
        f = __half22float2(h3); a[6] += f.x; a[7] += f.y;
    }
    #pragma unroll
    for (int i = 0; i < 8; i++) {
        a[i] += __shfl_xor_sync(0xFFFFFFFFu, a[i], 8);
        a[i] += __shfl_xor_sync(0xFFFFFFFFu, a[i], 16);
    }
}

// ---------------------------------------------------------------------
// 4) hop 1: y1[r] = fp16( dis[r]^2 * (sum_c y[c] + y[r]) )
//    (h1 = dr*(sum+y_r); y1 = dr*h1)
// ---------------------------------------------------------------------
__global__ void __launch_bounds__(128)
k_prop1(int n) {
    int warp = (blockIdx.x * blockDim.x + threadIdx.x) >> 5;
    int lane = threadIdx.x & 31;
    if (warp >= n) return;

    float a[8];
    gather_row_h(g_xh, g_rowptr[warp], g_rowptr[warp + 1], lane, a);

    if (lane < 8) {
        float dr = g_dis[warp];
        float t = dr * dr;
        uint4 ys = g_xh[(size_t)warp * R4H + lane];
        float2 f0 = __half22float2(*(__half2*)&ys.x);
        float2 f1 = __half22float2(*(__half2*)&ys.y);
        float2 f2 = __half22float2(*(__half2*)&ys.z);
        float2 f3 = __half22float2(*(__half2*)&ys.w);
        float o0 = t * (a[0] + f0.x);
        float o1 = t * (a[1] + f0.y);
        float o2 = t * (a[2] + f1.x);
        float o3 = t * (a[3] + f1.y);
        float o4 = t * (a[4] + f2.x);
        float o5 = t * (a[5] + f2.y);
        float o6 = t * (a[6] + f3.x);
        float o7 = t * (a[7] + f3.y);
        __half2 h;
        uint4 st;
        h = __floats2half2_rn(o0, o1); st.x = *(unsigned*)&h;
        h = __floats2half2_rn(o2, o3); st.y = *(unsigned*)&h;
        h = __floats2half2_rn(o4, o5); st.z = *(unsigned*)&h;
        h = __floats2half2_rn(o6, o7); st.w = *(unsigned*)&h;
        g_xh1[(size_t)warp * R4H + lane] = st;
    }
}

// ---------------------------------------------------------------------
// 5) fused hop 2 + GEMM + log_softmax.
//    h2[r] = dis[r] * (sum_c y1[c] + y1[r])  -> hs tile -> mma epilogue.
// ---------------------------------------------------------------------
#define HS_STRIDE 9
#define WS_STRIDE 42
__global__ void __launch_bounds__(256)
k_prop2_gemm(const float* __restrict__ W, const float* __restrict__ b,
             float* __restrict__ out, int n) {
    __shared__ uint4 hs[128 * HS_STRIDE];
    __shared__ float Ws[DD * WS_STRIDE];
    __shared__ float bs[CC];

    const int tid  = threadIdx.x;
    const int warp = tid >> 5;
    const int lane = tid & 31;
    const int row0 = blockIdx.x * 128;

    for (int i = tid; i < DD * CC; i += 256) {
        int k = i / CC, c = i % CC;
        Ws[k * WS_STRIDE + c] = W[i];
    }
    if (tid < CC) bs[tid] = b[tid];

    // ---- hop 2 for this block's 128 rows ----
    for (int rr = 0; rr < 16; rr++) {
        int r = warp * 16 + rr;
        int row = row0 + r;
        if (row < n) {
            float a[8];
            gather_row_h(g_xh1, g_rowptr[row], g_rowptr[row + 1], lane, a);
            if (lane < 8) {
                float dr = g_dis[row];
                uint4 ys = g_xh1[(size_t)row * R4H + lane];
                float2 f0 = __half22float2(*(__half2*)&ys.x);
                float2 f1 = __half22float2(*(__half2*)&ys.y);
                float2 f2 = __half22float2(*(__half2*)&ys.z);
                float2 f3 = __half22float2(*(__half2*)&ys.w);
                float o0 = dr * (a[0] + f0.x);
                float o1 = dr * (a[1] + f0.y);
                float o2 = dr * (a[2] + f1.x);
                float o3 = dr * (a[3] + f1.y);
                float o4 = dr * (a[4] + f2.x);
                float o5 = dr * (a[5] + f2.y);
                float o6 = dr * (a[6] + f3.x);
                float o7 = dr * (a[7] + f3.y);
                __half2 h;
                uint4 st;
                h = __floats2half2_rn(o0, o1); st.x = *(unsigned*)&h;
                h = __floats2half2_rn(o2, o3); st.y = *(unsigned*)&h;
                h = __floats2half2_rn(o4, o5); st.z = *(unsigned*)&h;
                h = __floats2half2_rn(o6, o7); st.w = *(unsigned*)&h;
                hs[r * HS_STRIDE + lane] = st;
            }
        } else if (lane < 8) {
            hs[r * HS_STRIDE + lane] = make_uint4(0u, 0u, 0u, 0u);
        }
    }
    __syncthreads();

    // ---- A fragments via ldmatrix ----
    unsigned hs_base = (unsigned)__cvta_generic_to_shared(hs);
    unsigned A[4][4];
    {
        int r_in = lane & 15;
        int half16 = (lane >> 4) * 16;
        unsigned rowaddr = hs_base + (unsigned)((warp * 16 + r_in) * (HS_STRIDE * 16)) + half16;
        #pragma unroll
        for (int kt = 0; kt < 4; kt++) {
            unsigned addr = rowaddr + kt * 32;
            asm volatile("ldmatrix.sync.aligned.m8n8.x4.shared.b16 {%0,%1,%2,%3}, [%4];"
                         : "=r"(A[kt][0]), "=r"(A[kt][1]), "=r"(A[kt][2]), "=r"(A[kt][3])
                         : "r"(addr));
        }
    }

    const int t = lane & 3, g = lane >> 2;
    float C[5][4];
    #pragma unroll
    for (int nt = 0; nt < 5; nt++) {
        int col0 = nt * 8 + 2 * t;
        float bi0 = bs[col0], bi1 = bs[col0 + 1];
        C[nt][0] = bi0; C[nt][1] = bi1; C[nt][2] = bi0; C[nt][3] = bi1;
        int nn = nt * 8 + g;
        #pragma unroll
        for (int kt = 0; kt < 4; kt++) {
            int k0 = kt * 16 + 2 * t;
            __half2 hb0 = __floats2half2_rn(Ws[k0 * WS_STRIDE + nn],
                                            Ws[(k0 + 1) * WS_STRIDE + nn]);
            __half2 hb1 = __floats2half2_rn(Ws[(k0 + 8) * WS_STRIDE + nn],
                                            Ws[(k0 + 9) * WS_STRIDE + nn]);
            unsigned B0 = *(unsigned*)&hb0;
            unsigned B1 = *(unsigned*)&hb1;
            asm volatile(
                "mma.sync.aligned.m16n8k16.row.col.f32.f16.f16.f32 "
                "{%0,%1,%2,%3}, {%4,%5,%6,%7}, {%8,%9}, {%0,%1,%2,%3};"
                : "+f"(C[nt][0]), "+f"(C[nt][1]), "+f"(C[nt][2]), "+f"(C[nt][3])
                : "r"(A[kt][0]), "r"(A[kt][1]), "r"(A[kt][2]), "r"(A[kt][3]),
                  "r"(B0), "r"(B1));
        }
    }

    float m0 = -1e30f, m1 = -1e30f;
    #pragma unroll
    for (int nt = 0; nt < 5; nt++) {
        m0 = fmaxf(m0, fmaxf(C[nt][0], C[nt][1]));
        m1 = fmaxf(m1, fmaxf(C[nt][2], C[nt][3]));
    }
    m0 = fmaxf(m0, __shfl_xor_sync(0xFFFFFFFFu, m0, 1));
    m0 = fmaxf(m0, __shfl_xor_sync(0xFFFFFFFFu, m0, 2));
    m1 = fmaxf(m1, __shfl_xor_sync(0xFFFFFFFFu, m1, 1));
    m1 = fmaxf(m1, __shfl_xor_sync(0xFFFFFFFFu, m1, 2));

    float s0 = 0.f, s1 = 0.f;
    #pragma unroll
    for (int nt = 0; nt < 5; nt++) {
        s0 += __expf(C[nt][0] - m0) + __expf(C[nt][1] - m0);
        s1 += __expf(C[nt][2] - m1) + __expf(C[nt][3] - m1);
    }
    s0 += __shfl_xor_sync(0xFFFFFFFFu, s0, 1);
    s0 += __shfl_xor_sync(0xFFFFFFFFu, s0, 2);
    s1 += __shfl_xor_sync(0xFFFFFFFFu, s1, 1);
    s1 += __shfl_xor_sync(0xFFFFFFFFu, s1, 2);

    float lse0 = m0 + __logf(s0);
    float lse1 = m1 + __logf(s1);

    int grow0 = row0 + warp * 16 + g;
    int grow1 = grow0 + 8;
    #pragma unroll
    for (int nt = 0; nt < 5; nt++) {
        int col0 = nt * 8 + 2 * t;
        if (grow0 < n)
            *(float2*)(out + (size_t)grow0 * CC + col0) =
                make_float2(C[nt][0] - lse0, C[nt][1] - lse0);
        if (grow1 < n)
            *(float2*)(out + (size_t)grow1 * CC + col0) =
                make_float2(C[nt][2] - lse1, C[nt][3] - lse1);
    }
}

// ---------------------------------------------------------------------
extern "C" void kernel_launch(void* const* d_in, const int* in_sizes, int n_in,
                              void* d_out, int out_size) {
    const float* x  = (const float*)d_in[0];
    const void*  ei = (const void*)d_in[1];
    const float* W  = (const float*)d_in[2];
    const float* b  = (const float*)d_in[3];
    float* out = (float*)d_out;

    const int n = NN, e = EE;
    const int T = 256;
    const int epairs = e / 2;               // 800000 == NN*R4H

    k_count     <<<(epairs + T - 1) / T, T>>>(ei, e);
    k_scan      <<<NBLK_SCAN, 1024>>>(n, e);
    k_fill      <<<(epairs + T - 1) / T, T>>>(ei, (const float4*)x, e);

    int prop_blocks = (n * 32 + 127) / 128;   // warp per row, 128-thread blocks
    k_prop1     <<<prop_blocks, 128>>>(n);
    k_prop2_gemm<<<(n + 127) / 128, T>>>(W, b, out, n);
}